// round 13
// baseline (speedup 1.0000x reference)
#include <cuda_runtime.h>
#include <math.h>
#include <stdint.h>

// ---------------------------------------------------------------------------
// out[k] = sigmoid( concat(feature[a], feature[b]) @ W1 @ W2 @ W3 @ W4 + c )
// Collapsed affine form (no inter-layer activations):
//   v4 = W4[:,0] (64), v3 = W3 v4 (512), v2 = W2 v3 (1024), v1 = W1 v2 (1802)
//   c  = b1.v2 + b2.v3 + b3.v4 + b4[0]
//   s1[e] = feature[e] . v1[0:901], s2[e] = feature[e] . v1[901:1802]
//   out[k] = sigmoid(s1[a] + s2[b] + c)
//
// SINGLE mega-kernel (R9 pipeline: 296 x 288, 3-stage ring, 8-row tiles,
// static tile partition). Chain phases are ordered by POINT-TO-POINT flag
// counters (release = fence+atomicAdd per finished warp; acquire = spin to
// target) instead of full-grid barriers, so phases pipeline without convoys
// and uninvolved blocks go straight to the weight wait. Flags reset after the
// final barrier (all spins provably passed) -> launch-invariant for graphs.
// ---------------------------------------------------------------------------

#define N_ENT 20000
#define D     901
#define B_TR  100000
#define B_TE  25000
#define N_PAIR (B_TR + B_TE)

#define TILE_ROWS  8
#define TILE_BYTES (TILE_ROWS * D * 4)     // 28832, multiple of 16
#define N_TILES    (N_ENT / TILE_ROWS)     // 2500
#define STAGES     3
#define SC_GRID    296                     // 2 blocks per SM, all co-resident
#define SC_THREADS 288                     // 8 consumer warps + 1 producer warp
#define N_CONS     (SC_GRID * 256)         // 75776 consumer threads
#define SC_SMEM    (64 + STAGES * TILE_BYTES)   // 86560 bytes

__device__ __align__(16) float g_v3[512];
__device__ __align__(16) float g_v2[1024];
__device__ __align__(16) float g_v1[2 * D];    // collapsed weight vector
__device__ float g_c;
__device__ __align__(16) float g_s[2 * N_ENT]; // s1[e]=g_s[2e], s2[e]=g_s[2e+1]
__device__ unsigned long long g_bar;           // epoch grid barrier (never reset)
__device__ unsigned int g_f3, g_f2, g_f1, g_fc;  // phase flags (reset each launch)

// ---- mbarrier / bulk-copy primitives ----
__device__ __forceinline__ void mbar_init(uint32_t addr, uint32_t count) {
    asm volatile("mbarrier.init.shared.b64 [%0], %1;" :: "r"(addr), "r"(count) : "memory");
}
__device__ __forceinline__ void mbar_expect_tx(uint32_t addr, uint32_t bytes) {
    asm volatile("mbarrier.arrive.expect_tx.shared.b64 _, [%0], %1;"
                 :: "r"(addr), "r"(bytes) : "memory");
}
__device__ __forceinline__ void mbar_arrive(uint32_t addr) {
    asm volatile("mbarrier.arrive.shared.b64 _, [%0];" :: "r"(addr) : "memory");
}
__device__ __forceinline__ void mbar_wait(uint32_t addr, uint32_t parity) {
    asm volatile(
        "{\n\t.reg .pred P;\n\t"
        "WAIT_%=:\n\t"
        "mbarrier.try_wait.parity.acquire.cta.shared::cta.b64 P, [%0], %1, 0x989680;\n\t"
        "@P bra.uni DONE_%=;\n\t"
        "bra.uni WAIT_%=;\n\t"
        "DONE_%=:\n\t}"
        :: "r"(addr), "r"(parity) : "memory");
}
__device__ __forceinline__ void bulk_g2s(uint32_t dst_smem, const void* src_gmem,
                                         uint32_t bytes, uint32_t mbar) {
    asm volatile(
        "cp.async.bulk.shared::cluster.global.mbarrier::complete_tx::bytes [%0], [%1], %2, [%3];"
        :: "r"(dst_smem), "l"(src_gmem), "r"(bytes), "r"(mbar) : "memory");
}
// consumer-only (256 threads) block sync, named barrier 1
__device__ __forceinline__ void cons_sync() {
    asm volatile("bar.sync 1, 256;" ::: "memory");
}
// consumer-only grid barrier (final only): epoch-counter, one arrival per block
__device__ __forceinline__ void cons_grid_barrier() {
    __threadfence();            // release
    cons_sync();
    if (threadIdx.x == 0) {
        unsigned long long ticket = atomicAdd(&g_bar, 1ULL);
        unsigned long long target = (ticket / SC_GRID + 1ULL) * SC_GRID;
        while (*(volatile unsigned long long*)&g_bar < target) { }
    }
    cons_sync();
    __threadfence();            // acquire
}
// release: this warp's global writes, then count one arrival
__device__ __forceinline__ void flag_release(unsigned int* f, int lane) {
    if (lane == 0) { __threadfence(); atomicAdd(f, 1u); }
}
// acquire: spin (lane 0) until count target reached, then fence
__device__ __forceinline__ void flag_acquire(unsigned int* f, unsigned int tgt, int lane) {
    if (lane == 0) {
        while (*(volatile unsigned int*)f < tgt) __nanosleep(32);
    }
    __syncwarp();
    __threadfence();
}

__global__ void __launch_bounds__(SC_THREADS, 2) k_all(
        const float* __restrict__ feat,
        const float* __restrict__ W1, const float* __restrict__ b1,
        const float* __restrict__ W2, const float* __restrict__ b2,
        const float* __restrict__ W3, const float* __restrict__ b3,
        const float* __restrict__ W4, const float* __restrict__ b4,
        const int2* __restrict__ tr, const int2* __restrict__ te,
        float* __restrict__ out) {
    extern __shared__ __align__(16) unsigned char smem_raw[];
    uint32_t smem = (uint32_t)__cvta_generic_to_shared(smem_raw);
    float* smemf = (float*)smem_raw;
    const uint32_t mb_full    = smem;        // 3 x 8B at 0,8,16
    const uint32_t mb_empty   = smem + 24;   // 3 x 8B at 24,32,40
    const uint32_t stage_base = smem + 64;

    int tid = threadIdx.x;
    int b   = blockIdx.x;

    if (tid == 0) {
        #pragma unroll
        for (int s = 0; s < STAGES; s++) {
            mbar_init(mb_full  + 8u * s, 1);
            mbar_init(mb_empty + 8u * s, 8);
        }
    }
    __syncthreads();   // all 288: mbarriers visible before producer issues

    if (tid >= 256) {
        // ---- producer warp: stream feature immediately (independent of chain)
        if (tid == 256) {
            int it = 0;
            for (int t = b; t < N_TILES; t += SC_GRID, it++) {
                int s  = it % STAGES;
                int ph = ((it / STAGES) & 1) ^ 1;   // first use of each stage passes
                mbar_wait(mb_empty + 8u * s, ph);
                mbar_expect_tx(mb_full + 8u * s, TILE_BYTES);
                bulk_g2s(stage_base + (uint32_t)s * TILE_BYTES,
                         feat + (size_t)t * TILE_ROWS * D,
                         TILE_BYTES, mb_full + 8u * s);
            }
        }
        return;   // producer never touches consumer barriers
    }

    // ================= consumer threads (256 per block) =================
    int warp = tid >> 5, lane = tid & 31;
    int cw   = b * 8 + warp;                 // global consumer warp id (0..2367)

    // pair indices preloaded up front (independent; hides 1 MB idx DRAM read)
    int k0 = b * 256 + tid, k1 = k0 + N_CONS;
    int2 p0 = make_int2(0, 0), p1 = make_int2(0, 0);
    if (k0 < N_PAIR) p0 = (k0 < B_TR) ? __ldg(tr + k0) : __ldg(te + (k0 - B_TR));
    if (k1 < N_PAIR) p1 = (k1 < B_TR) ? __ldg(tr + k1) : __ldg(te + (k1 - B_TR));

    // ---- phase 1: v3 = W3 @ W4col, one row per warp (512 warps) ----
    if (cw < 512) {
        float w4a = __ldg(W4 + lane), w4b = __ldg(W4 + 32 + lane);
        const float* row = W3 + cw * 64;
        float a = fmaf(__ldg(row + lane), w4a, __ldg(row + lane + 32) * w4b);
        #pragma unroll
        for (int o = 16; o; o >>= 1) a += __shfl_down_sync(0xffffffffu, a, o);
        if (lane == 0) g_v3[cw] = a;
        flag_release(&g_f3, lane);
    }

    // ---- phase 2: v2 = W2 @ v3, one row per warp (1024 warps) ----
    if (cw < 1024) {
        flag_acquire(&g_f3, 512u, lane);
        const float4* row = (const float4*)W2 + (size_t)cw * 128;
        const float4* v   = (const float4*)g_v3;
        float acc = 0.f;
        #pragma unroll
        for (int i = 0; i < 4; i++) {
            int j = lane + 32 * i;
            float4 a4 = __ldg(row + j);
            float4 b4 = __ldg(v + j);
            acc = fmaf(a4.x, b4.x, acc);
            acc = fmaf(a4.y, b4.y, acc);
            acc = fmaf(a4.z, b4.z, acc);
            acc = fmaf(a4.w, b4.w, acc);
        }
        #pragma unroll
        for (int o = 16; o; o >>= 1) acc += __shfl_down_sync(0xffffffffu, acc, o);
        if (lane == 0) g_v2[cw] = acc;
        flag_release(&g_f2, lane);
    }

    // ---- phase 3: v1 = W1 @ v2 (1802 warps) ----
    if (cw < 2 * D) {
        flag_acquire(&g_f2, 1024u, lane);
        const float4* row = (const float4*)W1 + (size_t)cw * 256;
        const float4* v   = (const float4*)g_v2;
        float acc = 0.f;
        #pragma unroll
        for (int i = 0; i < 8; i++) {
            int j = lane + 32 * i;
            float4 a4 = __ldg(row + j);
            float4 b4 = __ldg(v + j);
            acc = fmaf(a4.x, b4.x, acc);
            acc = fmaf(a4.y, b4.y, acc);
            acc = fmaf(a4.z, b4.z, acc);
            acc = fmaf(a4.w, b4.w, acc);
        }
        #pragma unroll
        for (int o = 16; o; o >>= 1) acc += __shfl_down_sync(0xffffffffu, acc, o);
        if (lane == 0) g_v1[cw] = acc;
        flag_release(&g_f1, lane);
    }

    // ---- bias constant: block 0 (all its warps also did phases 1-3) ----
    if (b == 0) {
        flag_acquire(&g_f2, 1024u, lane);   // needs v2 (implies v3 done)
        __shared__ float red[8];
        float acc = 0.f;
        #pragma unroll
        for (int j = tid; j < 1024; j += 256) acc = fmaf(__ldg(b1 + j), g_v2[j], acc);
        #pragma unroll
        for (int j = tid; j < 512; j += 256)  acc = fmaf(__ldg(b2 + j), g_v3[j], acc);
        if (tid < 64)                         acc = fmaf(__ldg(b3 + tid), __ldg(W4 + tid), acc);
        #pragma unroll
        for (int o = 16; o; o >>= 1) acc += __shfl_down_sync(0xffffffffu, acc, o);
        if (lane == 0) red[warp] = acc;
        cons_sync();
        if (tid == 0) {
            float s = __ldg(b4);
            #pragma unroll
            for (int w = 0; w < 8; w++) s += red[w];
            g_c = s;
            __threadfence();
            atomicAdd(&g_fc, 1u);
        }
    }

    // ---- wait for v1 + c, then load weights into registers ----
    if (lane == 0) {
        while (*(volatile unsigned int*)&g_f1 < (unsigned)(2 * D) ||
               *(volatile unsigned int*)&g_fc < 1u) __nanosleep(32);
    }
    __syncwarp();
    __threadfence();

    float rw1[28], rw2[28];
    #pragma unroll
    for (int i = 0; i < 28; i++) {
        rw1[i] = __ldg(g_v1 + lane + 32 * i);
        rw2[i] = __ldg(g_v1 + D + lane + 32 * i);
    }
    float rw1t = 0.f, rw2t = 0.f;
    if (lane < 5) {
        rw1t = __ldg(g_v1 + 896 + lane);
        rw2t = __ldg(g_v1 + D + 896 + lane);
    }
    float c = g_c;

    // ---- scores: one row per warp per tile from the smem ring ----
    int it = 0;
    for (int t = b; t < N_TILES; t += SC_GRID, it++) {
        int s  = it % STAGES;
        int ph = (it / STAGES) & 1;
        mbar_wait(mb_full + 8u * s, ph);
        int rbase = 16 + s * (TILE_BYTES / 4) + warp * D;   // float idx of row
        float s1 = 0.f, s2 = 0.f;
        #pragma unroll
        for (int i = 0; i < 28; i++) {
            float f = smemf[rbase + lane + 32 * i];
            s1 = fmaf(f, rw1[i], s1);
            s2 = fmaf(f, rw2[i], s2);
        }
        if (lane < 5) {
            float f = smemf[rbase + 896 + lane];
            s1 = fmaf(f, rw1t, s1);
            s2 = fmaf(f, rw2t, s2);
        }
        #pragma unroll
        for (int o = 16; o; o >>= 1) {
            s1 += __shfl_down_sync(0xffffffffu, s1, o);
            s2 += __shfl_down_sync(0xffffffffu, s2, o);
        }
        if (lane == 0) {
            int row = t * TILE_ROWS + warp;
            g_s[2 * row]     = s1;
            g_s[2 * row + 1] = s2;
            mbar_arrive(mb_empty + 8u * s);   // after reduce: lanes done reading
        }
    }
    cons_grid_barrier();   // all g_s visible

    // ---- reset phase flags for next graph replay (all spins provably passed)
    if (b == 0 && tid == 0) {
        g_f3 = 0; g_f2 = 0; g_f1 = 0; g_fc = 0;
        __threadfence();
    }

    // ---- gather + sigmoid epilogue (pairs already in registers) ----
    if (k0 < N_PAIR) {
        float z = g_s[2 * p0.x] + g_s[2 * p0.y + 1] + c;
        out[k0] = 1.0f / (1.0f + __expf(-z));
    }
    if (k1 < N_PAIR) {
        float z = g_s[2 * p1.x] + g_s[2 * p1.y + 1] + c;
        out[k1] = 1.0f / (1.0f + __expf(-z));
    }
}

extern "C" void kernel_launch(void* const* d_in, const int* in_sizes, int n_in,
                              void* d_out, int out_size) {
    const float* feature = (const float*)d_in[0];   // [20000, 901]
    const float* W1      = (const float*)d_in[1];   // [1802, 1024]
    const float* b1      = (const float*)d_in[2];   // [1024]
    const float* W2      = (const float*)d_in[3];   // [1024, 512]
    const float* b2      = (const float*)d_in[4];   // [512]
    const float* W3      = (const float*)d_in[5];   // [512, 64]
    const float* b3      = (const float*)d_in[6];   // [64]
    const float* W4      = (const float*)d_in[7];   // [64, 1]
    const float* b4      = (const float*)d_in[8];   // [1]
    const int2*  tr      = (const int2*)d_in[9];    // [100000, 2]
    const int2*  te      = (const int2*)d_in[10];   // [25000, 2]
    float*       out     = (float*)d_out;

    cudaFuncSetAttribute(k_all, cudaFuncAttributeMaxDynamicSharedMemorySize, SC_SMEM);
    k_all<<<SC_GRID, SC_THREADS, SC_SMEM>>>(feature, W1, b1, W2, b2, W3, b3,
                                            W4, b4, tr, te, out);
}

// round 14
// speedup vs baseline: 1.9503x; 1.9503x over previous
#include <cuda_runtime.h>
#include <math.h>
#include <stdint.h>

// ---------------------------------------------------------------------------
// out[k] = sigmoid( concat(feature[a], feature[b]) @ W1 @ W2 @ W3 @ W4 + c )
// Collapsed affine form (no inter-layer activations):
//   v4 = W4[:,0] (64), v3 = W3 v4 (512), v2 = W2 v3 (1024), v1 = W1 v2 (1802)
//   c  = b1.v2 + b2.v3 + b3.v4 + b4[0]
//   s1[e] = feature[e] . v1[0:901], s2[e] = feature[e] . v1[901:1802]
//   out[k] = sigmoid(s1[a] + s2[b] + c)
//
// SINGLE mega-kernel (R9 pipeline, verbatim): 296 x 288, 3-stage ring of
// 8-row tiles, consumer-only epoch grid barriers between chain phases.
// NEW (tail balance): the ring carries EXACTLY 8 tiles per block (rows
// 0..18943); the leftover 1056 rows are dotted straight from global memory by
// consumer warps cw<1056 (one row per warp, coalesced scalar __ldcs) right
// after the weight load, overlapping the ring stream instead of forming a
// 9th-tile tail that the final barrier would wait out.
// ---------------------------------------------------------------------------

#define N_ENT 20000
#define D     901
#define B_TR  100000
#define B_TE  25000
#define N_PAIR (B_TR + B_TE)

#define TILE_ROWS  8
#define TILE_BYTES (TILE_ROWS * D * 4)     // 28832, multiple of 16
#define STAGES     3
#define SC_GRID    296                     // 2 blocks per SM, all co-resident
#define SC_THREADS 288                     // 8 consumer warps + 1 producer warp
#define N_CONS     (SC_GRID * 256)         // 75776 consumer threads
#define SC_SMEM    (64 + STAGES * TILE_BYTES)   // 86560 bytes
#define TILES_PER_BLOCK 8                  // exact: 296*8 = 2368 ring tiles
#define RING_ROWS  (SC_GRID * TILES_PER_BLOCK * TILE_ROWS)   // 18944
#define LEFT_ROWS  (N_ENT - RING_ROWS)     // 1056 rows via direct LDG

__device__ __align__(16) float g_v3[512];
__device__ __align__(16) float g_v2[1024];
__device__ __align__(16) float g_v1[2 * D];    // collapsed weight vector
__device__ float g_c;
__device__ __align__(16) float g_s[2 * N_ENT]; // s1[e]=g_s[2e], s2[e]=g_s[2e+1]
__device__ unsigned long long g_bar;           // epoch grid barrier (never reset)

// ---- mbarrier / bulk-copy primitives ----
__device__ __forceinline__ void mbar_init(uint32_t addr, uint32_t count) {
    asm volatile("mbarrier.init.shared.b64 [%0], %1;" :: "r"(addr), "r"(count) : "memory");
}
__device__ __forceinline__ void mbar_expect_tx(uint32_t addr, uint32_t bytes) {
    asm volatile("mbarrier.arrive.expect_tx.shared.b64 _, [%0], %1;"
                 :: "r"(addr), "r"(bytes) : "memory");
}
__device__ __forceinline__ void mbar_arrive(uint32_t addr) {
    asm volatile("mbarrier.arrive.shared.b64 _, [%0];" :: "r"(addr) : "memory");
}
__device__ __forceinline__ void mbar_wait(uint32_t addr, uint32_t parity) {
    asm volatile(
        "{\n\t.reg .pred P;\n\t"
        "WAIT_%=:\n\t"
        "mbarrier.try_wait.parity.acquire.cta.shared::cta.b64 P, [%0], %1, 0x989680;\n\t"
        "@P bra.uni DONE_%=;\n\t"
        "bra.uni WAIT_%=;\n\t"
        "DONE_%=:\n\t}"
        :: "r"(addr), "r"(parity) : "memory");
}
__device__ __forceinline__ void bulk_g2s(uint32_t dst_smem, const void* src_gmem,
                                         uint32_t bytes, uint32_t mbar) {
    asm volatile(
        "cp.async.bulk.shared::cluster.global.mbarrier::complete_tx::bytes [%0], [%1], %2, [%3];"
        :: "r"(dst_smem), "l"(src_gmem), "r"(bytes), "r"(mbar) : "memory");
}
// consumer-only (256 threads) block sync, named barrier 1
__device__ __forceinline__ void cons_sync() {
    asm volatile("bar.sync 1, 256;" ::: "memory");
}
// consumer-only grid barrier: epoch-counter, one arrival per block
__device__ __forceinline__ void cons_grid_barrier() {
    __threadfence();            // release
    cons_sync();
    if (threadIdx.x == 0) {
        unsigned long long ticket = atomicAdd(&g_bar, 1ULL);
        unsigned long long target = (ticket / SC_GRID + 1ULL) * SC_GRID;
        while (*(volatile unsigned long long*)&g_bar < target) { }
    }
    cons_sync();
    __threadfence();            // acquire
}

__global__ void __launch_bounds__(SC_THREADS, 2) k_all(
        const float* __restrict__ feat,
        const float* __restrict__ W1, const float* __restrict__ b1,
        const float* __restrict__ W2, const float* __restrict__ b2,
        const float* __restrict__ W3, const float* __restrict__ b3,
        const float* __restrict__ W4, const float* __restrict__ b4,
        const int2* __restrict__ tr, const int2* __restrict__ te,
        float* __restrict__ out) {
    extern __shared__ __align__(16) unsigned char smem_raw[];
    uint32_t smem = (uint32_t)__cvta_generic_to_shared(smem_raw);
    float* smemf = (float*)smem_raw;
    const uint32_t mb_full    = smem;        // 3 x 8B at 0,8,16
    const uint32_t mb_empty   = smem + 24;   // 3 x 8B at 24,32,40
    const uint32_t stage_base = smem + 64;

    int tid = threadIdx.x;
    int b   = blockIdx.x;

    if (tid == 0) {
        #pragma unroll
        for (int s = 0; s < STAGES; s++) {
            mbar_init(mb_full  + 8u * s, 1);
            mbar_init(mb_empty + 8u * s, 8);
        }
    }
    __syncthreads();   // all 288: mbarriers visible before producer issues

    if (tid >= 256) {
        // ---- producer warp: exactly 8 tiles per block, from t=0 ----
        if (tid == 256) {
            #pragma unroll 1
            for (int it = 0; it < TILES_PER_BLOCK; it++) {
                int t  = b + it * SC_GRID;            // < 2368
                int s  = it % STAGES;
                int ph = ((it / STAGES) & 1) ^ 1;     // first use of each stage passes
                mbar_wait(mb_empty + 8u * s, ph);
                mbar_expect_tx(mb_full + 8u * s, TILE_BYTES);
                bulk_g2s(stage_base + (uint32_t)s * TILE_BYTES,
                         feat + (size_t)t * TILE_ROWS * D,
                         TILE_BYTES, mb_full + 8u * s);
            }
        }
        return;   // producer never touches consumer barriers
    }

    // ================= consumer threads (256 per block) =================
    int warp = tid >> 5, lane = tid & 31;
    int cw   = b * 8 + warp;                 // global consumer warp id (0..2367)

    // pair indices preloaded up front (independent; hides 1 MB idx DRAM read)
    int k0 = b * 256 + tid, k1 = k0 + N_CONS;
    int2 p0 = make_int2(0, 0), p1 = make_int2(0, 0);
    if (k0 < N_PAIR) p0 = (k0 < B_TR) ? __ldg(tr + k0) : __ldg(te + (k0 - B_TR));
    if (k1 < N_PAIR) p1 = (k1 < B_TR) ? __ldg(tr + k1) : __ldg(te + (k1 - B_TR));

    // ---- phase 1: v3 = W3 @ W4col, one row per warp (512 warps) ----
    if (cw < 512) {
        float w4a = __ldg(W4 + lane), w4b = __ldg(W4 + 32 + lane);
        const float* row = W3 + cw * 64;
        float a = fmaf(__ldg(row + lane), w4a, __ldg(row + lane + 32) * w4b);
        #pragma unroll
        for (int o = 16; o; o >>= 1) a += __shfl_down_sync(0xffffffffu, a, o);
        if (lane == 0) g_v3[cw] = a;
    }
    cons_grid_barrier();

    // ---- phase 2: v2 = W2 @ v3, one row per warp (1024 warps) ----
    if (cw < 1024) {
        const float4* row = (const float4*)W2 + (size_t)cw * 128;
        const float4* v   = (const float4*)g_v3;
        float acc = 0.f;
        #pragma unroll
        for (int i = 0; i < 4; i++) {
            int j = lane + 32 * i;
            float4 a4 = __ldg(row + j);
            float4 b4 = __ldg(v + j);
            acc = fmaf(a4.x, b4.x, acc);
            acc = fmaf(a4.y, b4.y, acc);
            acc = fmaf(a4.z, b4.z, acc);
            acc = fmaf(a4.w, b4.w, acc);
        }
        #pragma unroll
        for (int o = 16; o; o >>= 1) acc += __shfl_down_sync(0xffffffffu, acc, o);
        if (lane == 0) g_v2[cw] = acc;
    }
    cons_grid_barrier();

    // ---- phase 3: v1 = W1 @ v2 (1802 warps); block 0 also computes c ----
    if (cw < 2 * D) {
        const float4* row = (const float4*)W1 + (size_t)cw * 256;
        const float4* v   = (const float4*)g_v2;
        float acc = 0.f;
        #pragma unroll
        for (int i = 0; i < 8; i++) {
            int j = lane + 32 * i;
            float4 a4 = __ldg(row + j);
            float4 b4 = __ldg(v + j);
            acc = fmaf(a4.x, b4.x, acc);
            acc = fmaf(a4.y, b4.y, acc);
            acc = fmaf(a4.z, b4.z, acc);
            acc = fmaf(a4.w, b4.w, acc);
        }
        #pragma unroll
        for (int o = 16; o; o >>= 1) acc += __shfl_down_sync(0xffffffffu, acc, o);
        if (lane == 0) g_v1[cw] = acc;
    }
    if (b == 0) {
        __shared__ float red[8];
        float acc = 0.f;
        #pragma unroll
        for (int j = tid; j < 1024; j += 256) acc = fmaf(__ldg(b1 + j), g_v2[j], acc);
        #pragma unroll
        for (int j = tid; j < 512; j += 256)  acc = fmaf(__ldg(b2 + j), g_v3[j], acc);
        if (tid < 64)                         acc = fmaf(__ldg(b3 + tid), __ldg(W4 + tid), acc);
        #pragma unroll
        for (int o = 16; o; o >>= 1) acc += __shfl_down_sync(0xffffffffu, acc, o);
        if (lane == 0) red[warp] = acc;
        cons_sync();
        if (tid == 0) {
            float s = __ldg(b4);
            #pragma unroll
            for (int w = 0; w < 8; w++) s += red[w];
            g_c = s;
        }
    }
    cons_grid_barrier();

    // ---- weights into registers ----
    float rw1[28], rw2[28];
    #pragma unroll
    for (int i = 0; i < 28; i++) {
        rw1[i] = __ldg(g_v1 + lane + 32 * i);
        rw2[i] = __ldg(g_v1 + D + lane + 32 * i);
    }
    float rw1t = 0.f, rw2t = 0.f;
    if (lane < 5) {
        rw1t = __ldg(g_v1 + 896 + lane);
        rw2t = __ldg(g_v1 + D + 896 + lane);
    }

    // ---- leftover rows 18944..19999 straight from global (1056 warps) ----
    if (cw < LEFT_ROWS) {
        int row = RING_ROWS + cw;
        const float* fr = feat + (size_t)row * D;
        float s1 = 0.f, s2 = 0.f;
        #pragma unroll
        for (int i = 0; i < 28; i++) {
            float f = __ldcs(fr + lane + 32 * i);
            s1 = fmaf(f, rw1[i], s1);
            s2 = fmaf(f, rw2[i], s2);
        }
        if (lane < 5) {
            float f = __ldcs(fr + 896 + lane);
            s1 = fmaf(f, rw1t, s1);
            s2 = fmaf(f, rw2t, s2);
        }
        #pragma unroll
        for (int o = 16; o; o >>= 1) {
            s1 += __shfl_down_sync(0xffffffffu, s1, o);
            s2 += __shfl_down_sync(0xffffffffu, s2, o);
        }
        if (lane == 0) {
            g_s[2 * row]     = s1;
            g_s[2 * row + 1] = s2;
        }
    }

    // ---- scores: 8 ring tiles per block, one row per warp per tile ----
    #pragma unroll 1
    for (int it = 0; it < TILES_PER_BLOCK; it++) {
        int t  = b + it * SC_GRID;
        int s  = it % STAGES;
        int ph = (it / STAGES) & 1;
        mbar_wait(mb_full + 8u * s, ph);
        int rbase = 16 + s * (TILE_BYTES / 4) + warp * D;   // float idx of row
        float s1 = 0.f, s2 = 0.f;
        #pragma unroll
        for (int i = 0; i < 28; i++) {
            float f = smemf[rbase + lane + 32 * i];
            s1 = fmaf(f, rw1[i], s1);
            s2 = fmaf(f, rw2[i], s2);
        }
        if (lane < 5) {
            float f = smemf[rbase + 896 + lane];
            s1 = fmaf(f, rw1t, s1);
            s2 = fmaf(f, rw2t, s2);
        }
        #pragma unroll
        for (int o = 16; o; o >>= 1) {
            s1 += __shfl_down_sync(0xffffffffu, s1, o);
            s2 += __shfl_down_sync(0xffffffffu, s2, o);
        }
        if (lane == 0) {
            int row = t * TILE_ROWS + warp;
            g_s[2 * row]     = s1;
            g_s[2 * row + 1] = s2;
            mbar_arrive(mb_empty + 8u * s);   // after reduce: lanes done reading
        }
    }
    cons_grid_barrier();   // all g_s visible

    // ---- gather + sigmoid epilogue (pairs already in registers) ----
    float c = g_c;
    if (k0 < N_PAIR) {
        float z = g_s[2 * p0.x] + g_s[2 * p0.y + 1] + c;
        out[k0] = 1.0f / (1.0f + __expf(-z));
    }
    if (k1 < N_PAIR) {
        float z = g_s[2 * p1.x] + g_s[2 * p1.y + 1] + c;
        out[k1] = 1.0f / (1.0f + __expf(-z));
    }
}

extern "C" void kernel_launch(void* const* d_in, const int* in_sizes, int n_in,
                              void* d_out, int out_size) {
    const float* feature = (const float*)d_in[0];   // [20000, 901]
    const float* W1      = (const float*)d_in[1];   // [1802, 1024]
    const float* b1      = (const float*)d_in[2];   // [1024]
    const float* W2      = (const float*)d_in[3];   // [1024, 512]
    const float* b2      = (const float*)d_in[4];   // [512]
    const float* W3      = (const float*)d_in[5];   // [512, 64]
    const float* b3      = (const float*)d_in[6];   // [64]
    const float* W4      = (const float*)d_in[7];   // [64, 1]
    const float* b4      = (const float*)d_in[8];   // [1]
    const int2*  tr      = (const int2*)d_in[9];    // [100000, 2]
    const int2*  te      = (const int2*)d_in[10];   // [25000, 2]
    float*       out     = (float*)d_out;

    cudaFuncSetAttribute(k_all, cudaFuncAttributeMaxDynamicSharedMemorySize, SC_SMEM);
    k_all<<<SC_GRID, SC_THREADS, SC_SMEM>>>(feature, W1, b1, W2, b2, W3, b3,
                                            W4, b4, tr, te, out);
}

// round 15
// speedup vs baseline: 1.9562x; 1.0030x over previous
#include <cuda_runtime.h>
#include <math.h>
#include <stdint.h>

// ---------------------------------------------------------------------------
// out[k] = sigmoid( concat(feature[a], feature[b]) @ W1 @ W2 @ W3 @ W4 + c )
// Collapsed affine form (no inter-layer activations):
//   v4 = W4[:,0] (64), v3 = W3 v4 (512), v2 = W2 v3 (1024), v1 = W1 v2 (1802)
//   c  = b1.v2 + b2.v3 + b3.v4 + b4[0]
//   s1[e] = feature[e] . v1[0:901], s2[e] = feature[e] . v1[901:1802]
//   out[k] = sigmoid(s1[a] + s2[b] + c)
//
// SINGLE mega-kernel, R9 pipeline verbatim (296 x 288, 3-stage ring of 8-row
// tiles, static partition, consumer-only epoch grid barriers). ONE change:
// consumers release their ring stage immediately after the last LDS of the
// tile has issued (warp-synchronous in-order issue => smem data already
// latched), so the 10-SHFL reduce and g_s store overlap the next bulk copy
// instead of holding the stage (~260 cyc/warp/tile of producer stall removed).
// ---------------------------------------------------------------------------

#define N_ENT 20000
#define D     901
#define B_TR  100000
#define B_TE  25000
#define N_PAIR (B_TR + B_TE)

#define TILE_ROWS  8
#define TILE_BYTES (TILE_ROWS * D * 4)     // 28832, multiple of 16
#define N_TILES    (N_ENT / TILE_ROWS)     // 2500
#define STAGES     3
#define SC_GRID    296                     // 2 blocks per SM, all co-resident
#define SC_THREADS 288                     // 8 consumer warps + 1 producer warp
#define N_CONS     (SC_GRID * 256)         // 75776 consumer threads
#define SC_SMEM    (64 + STAGES * TILE_BYTES)   // 86560 bytes

__device__ __align__(16) float g_v3[512];
__device__ __align__(16) float g_v2[1024];
__device__ __align__(16) float g_v1[2 * D];    // collapsed weight vector
__device__ float g_c;
__device__ __align__(16) float g_s[2 * N_ENT]; // s1[e]=g_s[2e], s2[e]=g_s[2e+1]
__device__ unsigned long long g_bar;           // epoch grid barrier (never reset)

// ---- mbarrier / bulk-copy primitives ----
__device__ __forceinline__ void mbar_init(uint32_t addr, uint32_t count) {
    asm volatile("mbarrier.init.shared.b64 [%0], %1;" :: "r"(addr), "r"(count) : "memory");
}
__device__ __forceinline__ void mbar_expect_tx(uint32_t addr, uint32_t bytes) {
    asm volatile("mbarrier.arrive.expect_tx.shared.b64 _, [%0], %1;"
                 :: "r"(addr), "r"(bytes) : "memory");
}
__device__ __forceinline__ void mbar_arrive(uint32_t addr) {
    asm volatile("mbarrier.arrive.shared.b64 _, [%0];" :: "r"(addr) : "memory");
}
__device__ __forceinline__ void mbar_wait(uint32_t addr, uint32_t parity) {
    asm volatile(
        "{\n\t.reg .pred P;\n\t"
        "WAIT_%=:\n\t"
        "mbarrier.try_wait.parity.acquire.cta.shared::cta.b64 P, [%0], %1, 0x989680;\n\t"
        "@P bra.uni DONE_%=;\n\t"
        "bra.uni WAIT_%=;\n\t"
        "DONE_%=:\n\t}"
        :: "r"(addr), "r"(parity) : "memory");
}
__device__ __forceinline__ void bulk_g2s(uint32_t dst_smem, const void* src_gmem,
                                         uint32_t bytes, uint32_t mbar) {
    asm volatile(
        "cp.async.bulk.shared::cluster.global.mbarrier::complete_tx::bytes [%0], [%1], %2, [%3];"
        :: "r"(dst_smem), "l"(src_gmem), "r"(bytes), "r"(mbar) : "memory");
}
// consumer-only (256 threads) block sync, named barrier 1
__device__ __forceinline__ void cons_sync() {
    asm volatile("bar.sync 1, 256;" ::: "memory");
}
// consumer-only grid barrier: epoch-counter, one arrival per block
__device__ __forceinline__ void cons_grid_barrier() {
    __threadfence();            // release
    cons_sync();
    if (threadIdx.x == 0) {
        unsigned long long ticket = atomicAdd(&g_bar, 1ULL);
        unsigned long long target = (ticket / SC_GRID + 1ULL) * SC_GRID;
        while (*(volatile unsigned long long*)&g_bar < target) { }
    }
    cons_sync();
    __threadfence();            // acquire
}

__global__ void __launch_bounds__(SC_THREADS, 2) k_all(
        const float* __restrict__ feat,
        const float* __restrict__ W1, const float* __restrict__ b1,
        const float* __restrict__ W2, const float* __restrict__ b2,
        const float* __restrict__ W3, const float* __restrict__ b3,
        const float* __restrict__ W4, const float* __restrict__ b4,
        const int2* __restrict__ tr, const int2* __restrict__ te,
        float* __restrict__ out) {
    extern __shared__ __align__(16) unsigned char smem_raw[];
    uint32_t smem = (uint32_t)__cvta_generic_to_shared(smem_raw);
    float* smemf = (float*)smem_raw;
    const uint32_t mb_full    = smem;        // 3 x 8B at 0,8,16
    const uint32_t mb_empty   = smem + 24;   // 3 x 8B at 24,32,40
    const uint32_t stage_base = smem + 64;

    int tid = threadIdx.x;
    int b   = blockIdx.x;

    if (tid == 0) {
        #pragma unroll
        for (int s = 0; s < STAGES; s++) {
            mbar_init(mb_full  + 8u * s, 1);
            mbar_init(mb_empty + 8u * s, 8);
        }
    }
    __syncthreads();   // all 288: mbarriers visible before producer issues

    if (tid >= 256) {
        // ---- producer warp: stream feature immediately (independent of chain)
        if (tid == 256) {
            int it = 0;
            for (int t = b; t < N_TILES; t += SC_GRID, it++) {
                int s  = it % STAGES;
                int ph = ((it / STAGES) & 1) ^ 1;   // first use of each stage passes
                mbar_wait(mb_empty + 8u * s, ph);
                mbar_expect_tx(mb_full + 8u * s, TILE_BYTES);
                bulk_g2s(stage_base + (uint32_t)s * TILE_BYTES,
                         feat + (size_t)t * TILE_ROWS * D,
                         TILE_BYTES, mb_full + 8u * s);
            }
        }
        return;   // producer never touches consumer barriers
    }

    // ================= consumer threads (256 per block) =================
    int warp = tid >> 5, lane = tid & 31;
    int cw   = b * 8 + warp;                 // global consumer warp id (0..2367)

    // pair indices preloaded up front (independent; hides 1 MB idx DRAM read)
    int k0 = b * 256 + tid, k1 = k0 + N_CONS;
    int2 p0 = make_int2(0, 0), p1 = make_int2(0, 0);
    if (k0 < N_PAIR) p0 = (k0 < B_TR) ? __ldg(tr + k0) : __ldg(te + (k0 - B_TR));
    if (k1 < N_PAIR) p1 = (k1 < B_TR) ? __ldg(tr + k1) : __ldg(te + (k1 - B_TR));

    // ---- phase 1: v3 = W3 @ W4col, one row per warp (512 warps) ----
    if (cw < 512) {
        float w4a = __ldg(W4 + lane), w4b = __ldg(W4 + 32 + lane);
        const float* row = W3 + cw * 64;
        float a = fmaf(__ldg(row + lane), w4a, __ldg(row + lane + 32) * w4b);
        #pragma unroll
        for (int o = 16; o; o >>= 1) a += __shfl_down_sync(0xffffffffu, a, o);
        if (lane == 0) g_v3[cw] = a;
    }
    cons_grid_barrier();

    // ---- phase 2: v2 = W2 @ v3, one row per warp (1024 warps) ----
    if (cw < 1024) {
        const float4* row = (const float4*)W2 + (size_t)cw * 128;
        const float4* v   = (const float4*)g_v3;
        float acc = 0.f;
        #pragma unroll
        for (int i = 0; i < 4; i++) {
            int j = lane + 32 * i;
            float4 a4 = __ldg(row + j);
            float4 b4 = __ldg(v + j);
            acc = fmaf(a4.x, b4.x, acc);
            acc = fmaf(a4.y, b4.y, acc);
            acc = fmaf(a4.z, b4.z, acc);
            acc = fmaf(a4.w, b4.w, acc);
        }
        #pragma unroll
        for (int o = 16; o; o >>= 1) acc += __shfl_down_sync(0xffffffffu, acc, o);
        if (lane == 0) g_v2[cw] = acc;
    }
    cons_grid_barrier();

    // ---- phase 3: v1 = W1 @ v2 (1802 warps); block 0 also computes c ----
    if (cw < 2 * D) {
        const float4* row = (const float4*)W1 + (size_t)cw * 256;
        const float4* v   = (const float4*)g_v2;
        float acc = 0.f;
        #pragma unroll
        for (int i = 0; i < 8; i++) {
            int j = lane + 32 * i;
            float4 a4 = __ldg(row + j);
            float4 b4 = __ldg(v + j);
            acc = fmaf(a4.x, b4.x, acc);
            acc = fmaf(a4.y, b4.y, acc);
            acc = fmaf(a4.z, b4.z, acc);
            acc = fmaf(a4.w, b4.w, acc);
        }
        #pragma unroll
        for (int o = 16; o; o >>= 1) acc += __shfl_down_sync(0xffffffffu, acc, o);
        if (lane == 0) g_v1[cw] = acc;
    }
    if (b == 0) {
        __shared__ float red[8];
        float acc = 0.f;
        #pragma unroll
        for (int j = tid; j < 1024; j += 256) acc = fmaf(__ldg(b1 + j), g_v2[j], acc);
        #pragma unroll
        for (int j = tid; j < 512; j += 256)  acc = fmaf(__ldg(b2 + j), g_v3[j], acc);
        if (tid < 64)                         acc = fmaf(__ldg(b3 + tid), __ldg(W4 + tid), acc);
        #pragma unroll
        for (int o = 16; o; o >>= 1) acc += __shfl_down_sync(0xffffffffu, acc, o);
        if (lane == 0) red[warp] = acc;
        cons_sync();
        if (tid == 0) {
            float s = __ldg(b4);
            #pragma unroll
            for (int w = 0; w < 8; w++) s += red[w];
            g_c = s;
        }
    }
    cons_grid_barrier();

    // ---- weights into registers ----
    float rw1[28], rw2[28];
    #pragma unroll
    for (int i = 0; i < 28; i++) {
        rw1[i] = __ldg(g_v1 + lane + 32 * i);
        rw2[i] = __ldg(g_v1 + D + lane + 32 * i);
    }
    float rw1t = 0.f, rw2t = 0.f;
    if (lane < 5) {
        rw1t = __ldg(g_v1 + 896 + lane);
        rw2t = __ldg(g_v1 + D + 896 + lane);
    }

    // ---- scores: one row per warp per tile; EARLY stage release ----
    int it = 0;
    for (int t = b; t < N_TILES; t += SC_GRID, it++) {
        int s  = it % STAGES;
        int ph = (it / STAGES) & 1;
        mbar_wait(mb_full + 8u * s, ph);
        int rbase = 16 + s * (TILE_BYTES / 4) + warp * D;   // float idx of row
        float s1 = 0.f, s2 = 0.f;
        #pragma unroll
        for (int i = 0; i < 28; i++) {
            float f = smemf[rbase + lane + 32 * i];
            s1 = fmaf(f, rw1[i], s1);
            s2 = fmaf(f, rw2[i], s2);
        }
        if (lane < 5) {
            float f = smemf[rbase + 896 + lane];
            s1 = fmaf(f, rw1t, s1);
            s2 = fmaf(f, rw2t, s2);
        }
        // All lanes' LDS for this stage have ISSUED (warp-synchronous, in-order
        // issue) => smem contents already latched into the loads. Release the
        // stage now; the 10-SHFL reduce + g_s store overlap the next copy.
        if (lane == 0) mbar_arrive(mb_empty + 8u * s);
        #pragma unroll
        for (int o = 16; o; o >>= 1) {
            s1 += __shfl_down_sync(0xffffffffu, s1, o);
            s2 += __shfl_down_sync(0xffffffffu, s2, o);
        }
        if (lane == 0) {
            int row = t * TILE_ROWS + warp;
            g_s[2 * row]     = s1;
            g_s[2 * row + 1] = s2;
        }
    }
    cons_grid_barrier();   // all g_s visible

    // ---- gather + sigmoid epilogue (pairs already in registers) ----
    float c = g_c;
    if (k0 < N_PAIR) {
        float z = g_s[2 * p0.x] + g_s[2 * p0.y + 1] + c;
        out[k0] = 1.0f / (1.0f + __expf(-z));
    }
    if (k1 < N_PAIR) {
        float z = g_s[2 * p1.x] + g_s[2 * p1.y + 1] + c;
        out[k1] = 1.0f / (1.0f + __expf(-z));
    }
}

extern "C" void kernel_launch(void* const* d_in, const int* in_sizes, int n_in,
                              void* d_out, int out_size) {
    const float* feature = (const float*)d_in[0];   // [20000, 901]
    const float* W1      = (const float*)d_in[1];   // [1802, 1024]
    const float* b1      = (const float*)d_in[2];   // [1024]
    const float* W2      = (const float*)d_in[3];   // [1024, 512]
    const float* b2      = (const float*)d_in[4];   // [512]
    const float* W3      = (const float*)d_in[5];   // [512, 64]
    const float* b3      = (const float*)d_in[6];   // [64]
    const float* W4      = (const float*)d_in[7];   // [64, 1]
    const float* b4      = (const float*)d_in[8];   // [1]
    const int2*  tr      = (const int2*)d_in[9];    // [100000, 2]
    const int2*  te      = (const int2*)d_in[10];   // [25000, 2]
    float*       out     = (float*)d_out;

    cudaFuncSetAttribute(k_all, cudaFuncAttributeMaxDynamicSharedMemorySize, SC_SMEM);
    k_all<<<SC_GRID, SC_THREADS, SC_SMEM>>>(feature, W1, b1, W2, b2, W3, b3,
                                            W4, b4, tr, te, out);
}